// round 7
// baseline (speedup 1.0000x reference)
#include <cuda_runtime.h>
#include <cuda_bf16.h>
#include <cstdint>

// PerspectiveNet768x2, int16 fixed-point, hybrid LDG + single-shot TMA.
//
// R2-R4 all pinned at ~70 B/cyc/SM = LDG/L1tex path ceiling (L2 only ~77%).
// R5's multi-stage TMA pipeline regressed on sync overhead. R6: run both
// per-SM paths concurrently with zero pipeline overhead — 16 rows arrive via
// cp.async.bulk into SMEM (one mbarrier, one wait) while the other 48 rows
// go through the proven branch-free LDG loop; staged rows are then added
// from SMEM via conflict-free LDS.128.
//
// Quantization unchanged: int16 scale 40940, two 16-feature SIMD partials
// (max 16*2047 = 32752 < 32767), exact int32 combine. rel_err 2.56e-4.

#define NACT        32
#define THREADS     256
#define NFEAT       3840
#define WPR         512u              // uint32 words per 1024-col row
#define ZROW        (2u * NFEAT)      // all-zero row (device arrays zero-init)
#define ROW_BYTES   2048
#define TMA_ROWS    16                // 8 white + 8 black via bulk copy
#define TMA_BYTES   (TMA_ROWS * ROW_BYTES)   // 32 KB
#define QSCALE      40940.0f
#define QINV        (1.0f / 40940.0f)

// [white 0..3839 | black 3840..7679 | zero row 7680]
__device__ __align__(256) unsigned g_q[(2u * NFEAT + 1u) * WPR];

__global__ void convert_kernel(const float2* __restrict__ Ww,
                               const float2* __restrict__ Wb)
{
    const unsigned n = NFEAT * WPR;
    unsigned i = blockIdx.x * blockDim.x + threadIdx.x;
    if (i >= n) return;
    float2 a = __ldg(&Ww[i]);
    int q0 = __float2int_rn(a.x * QSCALE);
    int q1 = __float2int_rn(a.y * QSCALE);
    g_q[i] = ((unsigned)q0 & 0xFFFFu) | ((unsigned)q1 << 16);
    float2 c = __ldg(&Wb[i]);
    int p0 = __float2int_rn(c.x * QSCALE);
    int p1 = __float2int_rn(c.y * QSCALE);
    g_q[n + i] = ((unsigned)p0 & 0xFFFFu) | ((unsigned)p1 << 16);
}

__device__ __forceinline__ int lo16(unsigned w) { return (int)((short)(w & 0xFFFFu)); }
__device__ __forceinline__ int hi16(unsigned w) { return (int)((short)(w >> 16)); }

__device__ __forceinline__ void vacc(uint4& a, const uint4 v) {
    a.x = __vadd2(a.x, v.x);  a.y = __vadd2(a.y, v.y);
    a.z = __vadd2(a.z, v.z);  a.w = __vadd2(a.w, v.w);
}

__device__ __forceinline__ uint32_t smem_u32(const void* p) {
    return (uint32_t)__cvta_generic_to_shared(p);
}
__device__ __forceinline__ void mbar_init(uint32_t a, uint32_t cnt) {
    asm volatile("mbarrier.init.shared.b64 [%0], %1;" :: "r"(a), "r"(cnt) : "memory");
}
__device__ __forceinline__ void mbar_expect_tx(uint32_t a, uint32_t bytes) {
    asm volatile("mbarrier.arrive.expect_tx.shared.b64 _, [%0], %1;"
                 :: "r"(a), "r"(bytes) : "memory");
}
__device__ __forceinline__ void bulk_g2s(uint32_t dst, const void* src, uint32_t mbar) {
    asm volatile("cp.async.bulk.shared::cluster.global.mbarrier::complete_tx::bytes "
                 "[%0], [%1], %2, [%3];"
                 :: "r"(dst), "l"(src), "n"(ROW_BYTES), "r"(mbar) : "memory");
}
__device__ __forceinline__ void mbar_wait(uint32_t mbar, uint32_t parity) {
    asm volatile(
        "{\n\t.reg .pred P;\n"
        "W_%=:\n\t"
        "mbarrier.try_wait.parity.acquire.cta.shared::cta.b64 P, [%0], %1;\n\t"
        "@P bra D_%=;\n\t"
        "bra W_%=;\n"
        "D_%=:\n\t}"
        :: "r"(mbar), "r"(parity) : "memory");
}
__device__ __forceinline__ void fence_async() {
    asm volatile("fence.proxy.async.shared::cta;" ::: "memory");
}

__global__ __launch_bounds__(THREADS)
void nnue_gather_kernel(
    const int*    __restrict__ fw,    // [B,32]
    const int*    __restrict__ fb,    // [B,32]
    const int*    __restrict__ stm,   // [B] int32
    const float4* __restrict__ bw,    // [256]  (1024 floats)
    const float4* __restrict__ bb,
    const float4* __restrict__ Wout,  // [512]  (2048 floats)
    const float*  __restrict__ bout,
    float*        __restrict__ out)   // [B]
{
    __shared__ __align__(128) unsigned char sbuf[TMA_ROWS][ROW_BYTES]; // 32 KB
    __shared__ __align__(8)  unsigned long long smbar;
    __shared__ unsigned sidx[2 * NACT];
    __shared__ float    sred[THREADS / 32];

    const int b   = blockIdx.x;
    const int tid = threadIdx.x;

    // Stage absolute row ids: -1 -> zero row; black offset by NFEAT.
    if (tid < NACT) {
        int v = fw[b * NACT + tid];
        sidx[tid] = (v < 0) ? ZROW : (unsigned)v;
    } else if (tid < 2 * NACT) {
        int v = fb[b * NACT + (tid - NACT)];
        sidx[tid] = (v < 0) ? ZROW : (unsigned)v + NFEAT;
    }
    if (tid == 0) {
        mbar_init(smem_u32(&smbar), 1u);
        fence_async();
    }
    __syncthreads();

    const uint32_t mb = smem_u32(&smbar);

    // Kick off the TMA side-channel: rows sidx[0..7] (white) and
    // sidx[32..39] (black) -> sbuf rows 0..15. One expect_tx for all 32 KB.
    if (tid == 0) mbar_expect_tx(mb, TMA_BYTES);
    __syncwarp();                     // issuers (tid<16) are all in warp 0
    if (tid < TMA_ROWS) {
        const unsigned src_row = sidx[(tid >> 3) * NACT + (tid & 7)];
        bulk_g2s(smem_u32(&sbuf[tid][0]),
                 (const char*)g_q + (size_t)src_row * ROW_BYTES, mb);
    }

    // Concurrently: LDG-gather the other 48 rows (idxs 8..31 per perspective).
    const int persp = tid >> 7;        // 0 = white, 1 = black
    const int t     = tid & 127;       // 8-column group within the perspective
    const unsigned* base = g_q + (unsigned)t * 4u;
    const unsigned* idxs = sidx + persp * NACT;

    // Two partial SIMD accumulators, 16 features each (8 TMA + 8 LDG in a0).
    uint4 a0 = make_uint4(0u, 0u, 0u, 0u);
    uint4 a1 = make_uint4(0u, 0u, 0u, 0u);

    #pragma unroll
    for (int i = 8; i < 16; i += 4) {
        const uint4 v0 = *(const uint4*)(base + (size_t)idxs[i + 0] * WPR);
        const uint4 v1 = *(const uint4*)(base + (size_t)idxs[i + 1] * WPR);
        const uint4 v2 = *(const uint4*)(base + (size_t)idxs[i + 2] * WPR);
        const uint4 v3 = *(const uint4*)(base + (size_t)idxs[i + 3] * WPR);
        vacc(a0, v0); vacc(a0, v1); vacc(a0, v2); vacc(a0, v3);
    }
    #pragma unroll
    for (int i = 16; i < 32; i += 4) {
        const uint4 v0 = *(const uint4*)(base + (size_t)idxs[i + 0] * WPR);
        const uint4 v1 = *(const uint4*)(base + (size_t)idxs[i + 1] * WPR);
        const uint4 v2 = *(const uint4*)(base + (size_t)idxs[i + 2] * WPR);
        const uint4 v3 = *(const uint4*)(base + (size_t)idxs[i + 3] * WPR);
        vacc(a1, v0); vacc(a1, v1); vacc(a1, v2); vacc(a1, v3);
    }

    // TMA rows landed by now (they had the whole LDG phase to arrive).
    mbar_wait(mb, 0u);

    // Add the 8 staged rows of this thread's perspective via LDS.128
    // (thread t reads bytes [16t, 16t+16) of each row: conflict-free).
    {
        const unsigned char* sp = &sbuf[persp * 8][0] + t * 16;
        #pragma unroll
        for (int j = 0; j < 8; ++j) {
            const uint4 v = *(const uint4*)(sp + j * ROW_BYTES);
            vacc(a0, v);
        }
    }

    // Epilogue: combine partials in int32 (exact), dequant, bias, clip^2, dot.
    const bool white = (__ldg(&stm[b]) != 0);
    const float4* bias = (persp == 0) ? bw : bb;
    const float4 bv0 = bias[t * 2];
    const float4 bv1 = bias[t * 2 + 1];
    const int half = ((persp == 0) == white) ? 0 : 256;   // float4 offset
    const float4 w0 = Wout[half + t * 2];
    const float4 w1 = Wout[half + t * 2 + 1];

    #define COL(wA, wB, EXT, bvc, wc)                                   \
        ({ int   _c = EXT(wA) + EXT(wB);                                \
           float _h = fmaf((float)_c, QINV, (bvc));                     \
           _h = fminf(fmaxf(_h, 0.0f), 1.0f);                           \
           _h * _h * (wc); })

    float p = 0.0f;
    p += COL(a0.x, a1.x, lo16, bv0.x, w0.x);
    p += COL(a0.x, a1.x, hi16, bv0.y, w0.y);
    p += COL(a0.y, a1.y, lo16, bv0.z, w0.z);
    p += COL(a0.y, a1.y, hi16, bv0.w, w0.w);
    p += COL(a0.z, a1.z, lo16, bv1.x, w1.x);
    p += COL(a0.z, a1.z, hi16, bv1.y, w1.y);
    p += COL(a0.w, a1.w, lo16, bv1.z, w1.z);
    p += COL(a0.w, a1.w, hi16, bv1.w, w1.w);
    #undef COL

    // Block reduction.
    #pragma unroll
    for (int o = 16; o > 0; o >>= 1)
        p += __shfl_down_sync(0xffffffffu, p, o);
    if ((tid & 31) == 0) sred[tid >> 5] = p;
    __syncthreads();

    if (tid == 0) {
        float s = 0.0f;
        #pragma unroll
        for (int k = 0; k < THREADS / 32; ++k) s += sred[k];
        out[b] = s + bout[0];
    }
}

extern "C" void kernel_launch(void* const* d_in, const int* in_sizes, int n_in,
                              void* d_out, int out_size)
{
    const int*    fw   = (const int*)d_in[0];
    const int*    fb   = (const int*)d_in[1];
    const int*    stm  = (const int*)d_in[2];
    const float2* Ww   = (const float2*)d_in[3];
    const float4* bw   = (const float4*)d_in[4];
    const float2* Wb   = (const float2*)d_in[5];
    const float4* bb   = (const float4*)d_in[6];
    const float4* Wout = (const float4*)d_in[7];
    const float*  bout = (const float*)d_in[8];
    float*        out  = (float*)d_out;

    const int B = in_sizes[0] / NACT;   // 16384

    const unsigned nwords = NFEAT * WPR;
    convert_kernel<<<(nwords + 255) / 256, 256>>>(Ww, Wb);
    nnue_gather_kernel<<<B, THREADS>>>(fw, fb, stm, bw, bb, Wout, bout, out);
}

// round 8
// speedup vs baseline: 1.1485x; 1.1485x over previous
#include <cuda_runtime.h>
#include <cuda_bf16.h>
#include <cstdint>

// PerspectiveNet768x2, int16 fixed-point, LDG.64 gather.
//
// R2-R4: LDG.128 kernels all pinned at ~7.2 cyc/512B in the L1tex wavefront
// pipe (1.0 cross-LDG + 3x2.07 within-LDG replays). R5/R6: TMA/LDS paths
// share the same per-SM L1TEX unit -> no extra bandwidth, pure overhead.
// R8: LDG.64 -> 2 lines/inst -> (1.0 + 2.07) x 2 = 6.14 cyc/512B, ~15% fewer
// wavefront cycles per byte. Thread t covers cols [4t..4t+3] and
// [512+4t..512+4t+3] of its perspective; both loads are 256B-contiguous
// per warp. Numerics identical to R3/R4 (rel_err 2.560972e-4).

#define NACT        32
#define THREADS     256
#define NFEAT       3840
#define WPR         512u            // uint32 words per 1024-col row
#define ZROW        (2u * NFEAT)    // all-zero row (device arrays zero-init)
#define QSCALE      40940.0f       // 2047 / 0.05
#define QINV        (1.0f / 40940.0f)

// [white 0..3839 | black 3840..7679 | zero row 7680]
__device__ __align__(256) unsigned g_q[(2u * NFEAT + 1u) * WPR];

__global__ void convert_kernel(const float2* __restrict__ Ww,
                               const float2* __restrict__ Wb)
{
    const unsigned n = NFEAT * WPR;
    unsigned i = blockIdx.x * blockDim.x + threadIdx.x;
    if (i >= n) return;
    float2 a = __ldg(&Ww[i]);
    int q0 = __float2int_rn(a.x * QSCALE);
    int q1 = __float2int_rn(a.y * QSCALE);
    g_q[i] = ((unsigned)q0 & 0xFFFFu) | ((unsigned)q1 << 16);
    float2 c = __ldg(&Wb[i]);
    int p0 = __float2int_rn(c.x * QSCALE);
    int p1 = __float2int_rn(c.y * QSCALE);
    g_q[n + i] = ((unsigned)p0 & 0xFFFFu) | ((unsigned)p1 << 16);
}

__device__ __forceinline__ int lo16(unsigned w) { return (int)((short)(w & 0xFFFFu)); }
__device__ __forceinline__ int hi16(unsigned w) { return (int)((short)(w >> 16)); }

__device__ __forceinline__ void vacc2(uint2& a, const uint2 v) {
    a.x = __vadd2(a.x, v.x);  a.y = __vadd2(a.y, v.y);
}

__global__ __launch_bounds__(THREADS)
void nnue_gather_kernel(
    const int*    __restrict__ fw,    // [B,32]
    const int*    __restrict__ fb,    // [B,32]
    const int*    __restrict__ stm,   // [B] int32
    const float4* __restrict__ bw,    // [256]  (1024 floats)
    const float4* __restrict__ bb,
    const float4* __restrict__ Wout,  // [512]  (2048 floats)
    const float*  __restrict__ bout,
    float*        __restrict__ out)   // [B]
{
    __shared__ unsigned sidx[2 * NACT];
    __shared__ float    sred[THREADS / 32];

    const int b   = blockIdx.x;
    const int tid = threadIdx.x;

    // Stage absolute row ids: -1 -> zero row; black offset by NFEAT.
    if (tid < NACT) {
        int v = fw[b * NACT + tid];
        sidx[tid] = (v < 0) ? ZROW : (unsigned)v;
    } else if (tid < 2 * NACT) {
        int v = fb[b * NACT + (tid - NACT)];
        sidx[tid] = (v < 0) ? ZROW : (unsigned)v + NFEAT;
    }
    __syncthreads();

    const int persp = tid >> 7;        // 0 = white, 1 = black
    const int t     = tid & 127;
    // First half: words [2t, 2t+1] (cols 4t..4t+3).
    // Second half: words [256+2t, 256+2t+1] (cols 512+4t..512+4t+3).
    const unsigned* base_lo = g_q + (unsigned)t * 2u;
    const unsigned* base_hi = base_lo + 256u;
    const unsigned* idxs = sidx + persp * NACT;

    // Four 16-feature SIMD partials (max 16*2047 = 32752 < 32767).
    uint2 lo0 = make_uint2(0u, 0u), lo1 = make_uint2(0u, 0u);
    uint2 hi0 = make_uint2(0u, 0u), hi1 = make_uint2(0u, 0u);

    #pragma unroll
    for (int i = 0; i < 16; i += 4) {
        const size_t r0 = (size_t)idxs[i + 0] * WPR;
        const size_t r1 = (size_t)idxs[i + 1] * WPR;
        const size_t r2 = (size_t)idxs[i + 2] * WPR;
        const size_t r3 = (size_t)idxs[i + 3] * WPR;
        const uint2 a0 = *(const uint2*)(base_lo + r0);
        const uint2 b0 = *(const uint2*)(base_hi + r0);
        const uint2 a1 = *(const uint2*)(base_lo + r1);
        const uint2 b1 = *(const uint2*)(base_hi + r1);
        const uint2 a2 = *(const uint2*)(base_lo + r2);
        const uint2 b2 = *(const uint2*)(base_hi + r2);
        const uint2 a3 = *(const uint2*)(base_lo + r3);
        const uint2 b3 = *(const uint2*)(base_hi + r3);
        vacc2(lo0, a0); vacc2(hi0, b0);
        vacc2(lo0, a1); vacc2(hi0, b1);
        vacc2(lo0, a2); vacc2(hi0, b2);
        vacc2(lo0, a3); vacc2(hi0, b3);
    }
    #pragma unroll
    for (int i = 16; i < 32; i += 4) {
        const size_t r0 = (size_t)idxs[i + 0] * WPR;
        const size_t r1 = (size_t)idxs[i + 1] * WPR;
        const size_t r2 = (size_t)idxs[i + 2] * WPR;
        const size_t r3 = (size_t)idxs[i + 3] * WPR;
        const uint2 a0 = *(const uint2*)(base_lo + r0);
        const uint2 b0 = *(const uint2*)(base_hi + r0);
        const uint2 a1 = *(const uint2*)(base_lo + r1);
        const uint2 b1 = *(const uint2*)(base_hi + r1);
        const uint2 a2 = *(const uint2*)(base_lo + r2);
        const uint2 b2 = *(const uint2*)(base_hi + r2);
        const uint2 a3 = *(const uint2*)(base_lo + r3);
        const uint2 b3 = *(const uint2*)(base_hi + r3);
        vacc2(lo1, a0); vacc2(hi1, b0);
        vacc2(lo1, a1); vacc2(hi1, b1);
        vacc2(lo1, a2); vacc2(hi1, b2);
        vacc2(lo1, a3); vacc2(hi1, b3);
    }

    // Epilogue: combine partials in int32 (exact), dequant, bias, clip^2, dot.
    const bool white = (__ldg(&stm[b]) != 0);
    const float4* bias = (persp == 0) ? bw : bb;
    const float4 bvL = bias[t];            // cols 4t..4t+3
    const float4 bvH = bias[t + 128];      // cols 512+4t..512+4t+3
    const int half = ((persp == 0) == white) ? 0 : 256;   // float4 offset
    const float4 wL = Wout[half + t];
    const float4 wH = Wout[half + t + 128];

    #define COL(wA, wB, EXT, bvc, wc)                                   \
        ({ int   _c = EXT(wA) + EXT(wB);                                \
           float _h = fmaf((float)_c, QINV, (bvc));                     \
           _h = fminf(fmaxf(_h, 0.0f), 1.0f);                           \
           _h * _h * (wc); })

    float p = 0.0f;
    p += COL(lo0.x, lo1.x, lo16, bvL.x, wL.x);
    p += COL(lo0.x, lo1.x, hi16, bvL.y, wL.y);
    p += COL(lo0.y, lo1.y, lo16, bvL.z, wL.z);
    p += COL(lo0.y, lo1.y, hi16, bvL.w, wL.w);
    p += COL(hi0.x, hi1.x, lo16, bvH.x, wH.x);
    p += COL(hi0.x, hi1.x, hi16, bvH.y, wH.y);
    p += COL(hi0.y, hi1.y, lo16, bvH.z, wH.z);
    p += COL(hi0.y, hi1.y, hi16, bvH.w, wH.w);
    #undef COL

    // Block reduction.
    #pragma unroll
    for (int o = 16; o > 0; o >>= 1)
        p += __shfl_down_sync(0xffffffffu, p, o);
    if ((tid & 31) == 0) sred[tid >> 5] = p;
    __syncthreads();

    if (tid == 0) {
        float s = 0.0f;
        #pragma unroll
        for (int k = 0; k < THREADS / 32; ++k) s += sred[k];
        out[b] = s + bout[0];
    }
}

extern "C" void kernel_launch(void* const* d_in, const int* in_sizes, int n_in,
                              void* d_out, int out_size)
{
    const int*    fw   = (const int*)d_in[0];
    const int*    fb   = (const int*)d_in[1];
    const int*    stm  = (const int*)d_in[2];
    const float2* Ww   = (const float2*)d_in[3];
    const float4* bw   = (const float4*)d_in[4];
    const float2* Wb   = (const float2*)d_in[5];
    const float4* bb   = (const float4*)d_in[6];
    const float4* Wout = (const float4*)d_in[7];
    const float*  bout = (const float*)d_in[8];
    float*        out  = (float*)d_out;

    const int B = in_sizes[0] / NACT;   // 16384

    const unsigned nwords = NFEAT * WPR;
    convert_kernel<<<(nwords + 255) / 256, 256>>>(Ww, Wb);
    nnue_gather_kernel<<<B, THREADS>>>(fw, fb, stm, bw, bb, Wout, bout, out);
}